// round 6
// baseline (speedup 1.0000x reference)
#include <cuda_runtime.h>

// FixedRadiusNearNeighbors: B=8, N=16384, S=2048, radius 0.1, K=64.
// Output = first 64 ascending point indices with sqrdist <= 0.01f (padded
// with the first hit), written as FLOAT32 values (indices <= 16383 are
// exactly representable; hypothesis: harness compares f32).
//
// Distance arithmetic (cuBLAS-SIMT / Eigen k-loop semantics):
//   cc  = ((cx*cx + cy*cy) + cz*cz)          f32 RN mul/add
//   dot = fma(pz,cz, fma(py,cy, fma(px,cx, 0)))  ascending-k FMA chain
//   pp  = ((px*px + py*py) + pz*pz)          f32 RN mul/add
//   d   = (cc - 2*dot) + pp                  f32 RN, left-to-right
//   hit = !(d > 0.01f)

#define BATCH  8
#define NPTS   16384
#define NQ     2048
#define NNB    64
#define TILE   2048      // 2048 * 16B = 32 KB smem
#define WPB    8
#define R2     0.01f

__global__ __launch_bounds__(256)
void frnn_kernel(const float* __restrict__ pos,
                 const int*   __restrict__ cent,
                 float*       __restrict__ out)
{
    __shared__ float4 sp4[TILE];         // {x, y, z, pp}
    __shared__ int done_count;

    const int lane = threadIdx.x & 31;
    const int warp = threadIdx.x >> 5;
    const int q    = blockIdx.x * WPB + warp;
    const int b    = q >> 11;                      // q / NQ
    const float* posb = pos + (size_t)b * NPTS * 3;

    const int   c  = cent[q];
    const float cx = posb[c * 3 + 0];
    const float cy = posb[c * 3 + 1];
    const float cz = posb[c * 3 + 2];
    const float cc = __fadd_rn(__fadd_rn(__fmul_rn(cx, cx), __fmul_rn(cy, cy)),
                               __fmul_rn(cz, cz));

    float* orow = out + (size_t)q * NNB;

    if (threadIdx.x == 0) done_count = 0;

    int   cnt      = 0;
    float firstIdx = 0.0f;
    bool  imdone   = false;

    for (int base = 0; base < NPTS; base += TILE) {
        __syncthreads();                 // orders done_count + tile reuse
        if (done_count == WPB) break;

        // Cooperative tile load; precompute pp with reference rounding.
        const float* src = posb + (size_t)base * 3;
        #pragma unroll 2
        for (int i = threadIdx.x; i < TILE; i += 256) {
            float px = src[i * 3 + 0];
            float py = src[i * 3 + 1];
            float pz = src[i * 3 + 2];
            float pp = __fadd_rn(__fadd_rn(__fmul_rn(px, px), __fmul_rn(py, py)),
                                 __fmul_rn(pz, pz));
            sp4[i] = make_float4(px, py, pz, pp);
        }
        __syncthreads();

        if (!imdone) {
            #pragma unroll 4
            for (int i = lane; i < TILE; i += 32) {
                float4 p = sp4[i];       // LDS.128, conflict-free
                // ascending-k FMA chain, acc init 0
                float dot = __fmaf_rn(p.x, cx, 0.0f);
                dot = __fmaf_rn(p.y, cy, dot);
                dot = __fmaf_rn(p.z, cz, dot);
                float d = __fadd_rn(__fsub_rn(cc, __fmul_rn(2.0f, dot)), p.w);

                bool hit = !(d > R2);
                unsigned mask = __ballot_sync(0xffffffffu, hit);
                if (mask) {
                    if (cnt == 0) {
                        int leader = __ffs(mask) - 1;
                        int fi = __shfl_sync(0xffffffffu, base + i, leader);
                        firstIdx = (float)fi;      // exact: fi < 2^24
                    }
                    if (hit) {
                        int slot = cnt + __popc(mask & ((1u << lane) - 1u));
                        if (slot < NNB) orow[slot] = (float)(base + i);
                    }
                    cnt += __popc(mask);
                    if (cnt >= NNB) {
                        imdone = true;
                        if (lane == 0) atomicAdd(&done_count, 1);
                        break;
                    }
                }
            }
        }
    }

    // Pad tail with the first hit (group_first semantics).
    if (cnt > NNB) cnt = NNB;
    for (int s = cnt + lane; s < NNB; s += 32)
        orow[s] = firstIdx;
}

extern "C" void kernel_launch(void* const* d_in, const int* in_sizes, int n_in,
                              void* d_out, int out_size)
{
    const float* pos;
    const int*   cent;
    if (in_sizes[0] > in_sizes[1]) {
        pos  = (const float*)d_in[0];
        cent = (const int*)  d_in[1];
    } else {
        pos  = (const float*)d_in[1];
        cent = (const int*)  d_in[0];
    }
    float* out = (float*)d_out;                  // (8,2048,64) as float32

    dim3 grid(BATCH * NQ / WPB);
    dim3 block(256);
    frnn_kernel<<<grid, block>>>(pos, cent, out);
}